// round 15
// baseline (speedup 1.0000x reference)
#include <cuda_runtime.h>
#include <cuda_fp16.h>
#include <mma.h>
using namespace nvcuda;

static constexpr int NNODES = 10000;
static constexpr int NE     = 640000;
static constexpr int DIN    = 128;
static constexpr int DHID   = 256;
static constexpr int DOUT   = 64;
static constexpr int CAP    = 160;     // per-node bucket capacity (mean deg 64, sigma 8)

static constexpr int H_HALF2  = NNODES * DIN / 2;        // 640000
static constexpr int W1_HALF2 = 2 * DIN * DHID / 2;      // 32768
static constexpr int W2_HALF2 = 2 * DHID * DOUT / 2;     // 16384

// ---- scratch (__device__ globals: allocation-free rule) ----
__device__ int    g_cnt[NNODES];           // zero-init; invariant restored by gather2
__device__ int2   g_edges[NNODES * CAP];   // (src, w bits) bucketed by dst
__device__ __half g_hh [NNODES * DIN];     // h in fp16
__device__ __half g_hNh[NNODES * DIN];     // layer-1 mean aggregate, fp16
__device__ float  g_xacc[NNODES * DHID];   // h @ W1_top (fp32 partial)
__device__ __half g_xh [NNODES * DHID];    // layer-1 output (post relu), fp16
__device__ __half g_yh [NNODES * DOUT];    // x @ W2_bot, fp16
__device__ __half g_W1h[2 * DIN * DHID];   // W1 fp16 [256 x 256]
__device__ __half g_W2h[2 * DHID * DOUT];  // W2 fp16 [512 x 64]

// ---------------------------------------------------------------------------
// build: one pass, no scan.  pos = dst*CAP + rank
// ---------------------------------------------------------------------------
__global__ void build_kernel(const int* __restrict__ src, const int* __restrict__ dst,
                             const float* __restrict__ w) {
    int e = blockIdx.x * blockDim.x + threadIdx.x;
    if (e < NE) {
        int d = dst[e];
        int r = atomicAdd(&g_cnt[d], 1);
        g_edges[d * CAP + r] = make_int2(src[e], __float_as_int(w[e]));
    }
}

// ---------------------------------------------------------------------------
// cvt: h, W1, W2 -> fp16 (one launch)
// ---------------------------------------------------------------------------
__global__ void cvt_kernel(const float* __restrict__ h,
                           const float* __restrict__ W1,
                           const float* __restrict__ W2) {
    int i = blockIdx.x * blockDim.x + threadIdx.x;
    if (i < H_HALF2) {
        float2 v = reinterpret_cast<const float2*>(h)[i];
        reinterpret_cast<__half2*>(g_hh)[i] = __floats2half2_rn(v.x, v.y);
    } else if (i < H_HALF2 + W1_HALF2) {
        int k = i - H_HALF2;
        float2 v = reinterpret_cast<const float2*>(W1)[k];
        reinterpret_cast<__half2*>(g_W1h)[k] = __floats2half2_rn(v.x, v.y);
    } else if (i < H_HALF2 + W1_HALF2 + W2_HALF2) {
        int k = i - H_HALF2 - W1_HALF2;
        float2 v = reinterpret_cast<const float2*>(W2)[k];
        reinterpret_cast<__half2*>(g_W2h)[k] = __floats2half2_rn(v.x, v.y);
    }
}

// ---------------------------------------------------------------------------
// gather helpers
// ---------------------------------------------------------------------------
__device__ __forceinline__ void acc_uint4_f16(float* acc, uint4 r, float w) {
    float2 p0 = __half22float2(*reinterpret_cast<__half2*>(&r.x));
    float2 p1 = __half22float2(*reinterpret_cast<__half2*>(&r.y));
    float2 p2 = __half22float2(*reinterpret_cast<__half2*>(&r.z));
    float2 p3 = __half22float2(*reinterpret_cast<__half2*>(&r.w));
    acc[0] = fmaf(p0.x, w, acc[0]); acc[1] = fmaf(p0.y, w, acc[1]);
    acc[2] = fmaf(p1.x, w, acc[2]); acc[3] = fmaf(p1.y, w, acc[3]);
    acc[4] = fmaf(p2.x, w, acc[4]); acc[5] = fmaf(p2.y, w, acc[5]);
    acc[6] = fmaf(p3.x, w, acc[6]); acc[7] = fmaf(p3.y, w, acc[7]);
}

// ---------------------------------------------------------------------------
// gather1: hNh[n] = fp16( (1/deg) * sum h[src]*w )   (D=128)
// TWO warps per node: each handles half the edge list (halved serial chain),
// partials combined via smem.  Block = 256 thr = 8 warps = 4 nodes.
// ---------------------------------------------------------------------------
__global__ __launch_bounds__(256)
void gather1_kernel() {
    __shared__ float sm[4][128];

    int wid  = threadIdx.x >> 5;
    int lane = threadIdx.x & 31;
    int pair = wid >> 1;           // 0..3: node slot within block
    int role = wid & 1;            // 0 or 1: which half of edges
    int node = blockIdx.x * 4 + pair;

    int grp = lane >> 4;           // 0/1: edge interleave within warp
    int sub = lane & 15;           // column block: halves [sub*8, sub*8+8)

    float acc[8] = {};
    int deg = 0;

    if (node < NNODES) {
        deg = g_cnt[node];
        int half = (deg + 1) >> 1;
        int s = node * CAP + role * half;
        int e = node * CAP + ((role == 0) ? half : deg);

        int j = s;
        for (; j + 3 < e; j += 4) {
            int2 ea = g_edges[j + grp];
            int2 eb = g_edges[j + 2 + grp];
            uint4 ra = *reinterpret_cast<const uint4*>(g_hh + (size_t)ea.x * DIN + sub * 8);
            uint4 rb = *reinterpret_cast<const uint4*>(g_hh + (size_t)eb.x * DIN + sub * 8);
            acc_uint4_f16(acc, ra, __int_as_float(ea.y));
            acc_uint4_f16(acc, rb, __int_as_float(eb.y));
        }
        for (; j < e; j += 2) {
            if (j + grp < e) {
                int2 ea = g_edges[j + grp];
                uint4 ra = *reinterpret_cast<const uint4*>(g_hh + (size_t)ea.x * DIN + sub * 8);
                acc_uint4_f16(acc, ra, __int_as_float(ea.y));
            }
        }

#pragma unroll
        for (int k = 0; k < 8; ++k)
            acc[k] += __shfl_down_sync(0xffffffffu, acc[k], 16);
    }

    // role-1 warp deposits its partial into smem
    if (node < NNODES && role == 1 && lane < 16) {
#pragma unroll
        for (int k = 0; k < 8; ++k)
            sm[pair][sub * 8 + k] = acc[k];
    }
    __syncthreads();

    // role-0 warp combines, normalizes, stores
    if (node < NNODES && role == 0 && lane < 16) {
        float inv = (deg > 0) ? 1.0f / (float)deg : 0.0f;
#pragma unroll
        for (int k = 0; k < 8; ++k)
            acc[k] = (acc[k] + sm[pair][sub * 8 + k]) * inv;
        __half2 q0 = __floats2half2_rn(acc[0], acc[1]);
        __half2 q1 = __floats2half2_rn(acc[2], acc[3]);
        __half2 q2 = __floats2half2_rn(acc[4], acc[5]);
        __half2 q3 = __floats2half2_rn(acc[6], acc[7]);
        uint4 pk;
        pk.x = *reinterpret_cast<unsigned*>(&q0);
        pk.y = *reinterpret_cast<unsigned*>(&q1);
        pk.z = *reinterpret_cast<unsigned*>(&q2);
        pk.w = *reinterpret_cast<unsigned*>(&q3);
        *reinterpret_cast<uint4*>(g_hNh + (size_t)node * DIN + sub * 8) = pk;
    }
}

// ---------------------------------------------------------------------------
// gather2: out[n] += (1/deg) * sum y[src]*w     (D=64);  resets g_cnt
// ---------------------------------------------------------------------------
__global__ __launch_bounds__(256)
void gather2_kernel(float* __restrict__ out) {
    int gw = (blockIdx.x * blockDim.x + threadIdx.x) >> 5;
    if (gw >= NNODES) return;
    int lane = threadIdx.x & 31;
    int grp  = lane >> 3;
    int sub  = lane & 7;
    int deg = g_cnt[gw];
    int s = gw * CAP, e = s + deg;
    float acc[8] = {};

    int j = s;
    for (; j + 7 < e; j += 8) {
        int2 ea = g_edges[j + grp];
        int2 eb = g_edges[j + 4 + grp];
        uint4 ra = *reinterpret_cast<const uint4*>(g_yh + (size_t)ea.x * DOUT + sub * 8);
        uint4 rb = *reinterpret_cast<const uint4*>(g_yh + (size_t)eb.x * DOUT + sub * 8);
        acc_uint4_f16(acc, ra, __int_as_float(ea.y));
        acc_uint4_f16(acc, rb, __int_as_float(eb.y));
    }
    for (; j < e; j += 4) {
        if (j + grp < e) {
            int2 ea = g_edges[j + grp];
            uint4 ra = *reinterpret_cast<const uint4*>(g_yh + (size_t)ea.x * DOUT + sub * 8);
            acc_uint4_f16(acc, ra, __int_as_float(ea.y));
        }
    }

#pragma unroll
    for (int k = 0; k < 8; ++k) {
        acc[k] += __shfl_down_sync(0xffffffffu, acc[k], 16);
        acc[k] += __shfl_down_sync(0xffffffffu, acc[k], 8);
    }

    if (lane == 0) g_cnt[gw] = 0;   // restore zero-invariant for next invocation

    if (lane < 8) {
        float inv = (deg > 0) ? 1.0f / (float)deg : 0.0f;
        float* op = out + (size_t)gw * DOUT + sub * 8;
        float4 c0 = *reinterpret_cast<float4*>(op);
        float4 c1 = *reinterpret_cast<float4*>(op + 4);
        c0.x = fmaf(acc[0], inv, c0.x); c0.y = fmaf(acc[1], inv, c0.y);
        c0.z = fmaf(acc[2], inv, c0.z); c0.w = fmaf(acc[3], inv, c0.w);
        c1.x = fmaf(acc[4], inv, c1.x); c1.y = fmaf(acc[5], inv, c1.y);
        c1.z = fmaf(acc[6], inv, c1.z); c1.w = fmaf(acc[7], inv, c1.w);
        *reinterpret_cast<float4*>(op)     = c0;
        *reinterpret_cast<float4*>(op + 4) = c1;
    }
}

// ---------------------------------------------------------------------------
// gemm1_top (HMMA): g_xacc = hh @ W1h[0:128]   (fp32, no bias)
// ---------------------------------------------------------------------------
__global__ __launch_bounds__(128)
void gemm1_top_kernel() {
    constexpr int LDS = 72;
    __shared__ __align__(16) char sm[64 * LDS * 4];
    __half* As = reinterpret_cast<__half*>(sm);
    __half* Bs = reinterpret_cast<__half*>(sm) + 64 * LDS;
    float*  Cs = reinterpret_cast<float*>(sm);

    int tid  = threadIdx.x;
    int wid  = tid >> 5;
    int row0 = blockIdx.x * 64;
    int col0 = blockIdx.y * 64;
    int wy = wid >> 1, wx = wid & 1;
    int lr = tid >> 1;
    int lq = (tid & 1) * 32;

    wmma::fragment<wmma::accumulator, 16, 16, 16, float> acc[2][2];
#pragma unroll
    for (int i = 0; i < 2; ++i)
#pragma unroll
        for (int j = 0; j < 2; ++j)
            wmma::fill_fragment(acc[i][j], 0.0f);

    int  a_m  = row0 + lr;
    bool a_ok = (a_m < NNODES);

    for (int kb = 0; kb < 128; kb += 64) {
        const __half* abase = g_hh + (size_t)a_m * DIN + kb;
        uint4 av[4] = {};
        if (a_ok) {
#pragma unroll
            for (int q = 0; q < 4; ++q)
                av[q] = reinterpret_cast<const uint4*>(abase + lq)[q];
        }
#pragma unroll
        for (int q = 0; q < 4; ++q)
            reinterpret_cast<uint4*>(As + lr * LDS + lq)[q] = av[q];

        const __half* wb = g_W1h + (size_t)(kb + lr) * DHID + col0 + lq;
#pragma unroll
        for (int q = 0; q < 4; ++q)
            reinterpret_cast<uint4*>(Bs + lr * LDS + lq)[q] =
                reinterpret_cast<const uint4*>(wb)[q];

        __syncthreads();

#pragma unroll
        for (int ks = 0; ks < 4; ++ks) {
            wmma::fragment<wmma::matrix_a, 16, 16, 16, __half, wmma::row_major> af[2];
            wmma::fragment<wmma::matrix_b, 16, 16, 16, __half, wmma::row_major> bf[2];
            wmma::load_matrix_sync(af[0], As + (wy * 32 +  0) * LDS + ks * 16, LDS);
            wmma::load_matrix_sync(af[1], As + (wy * 32 + 16) * LDS + ks * 16, LDS);
            wmma::load_matrix_sync(bf[0], Bs + (ks * 16) * LDS + wx * 32 +  0, LDS);
            wmma::load_matrix_sync(bf[1], Bs + (ks * 16) * LDS + wx * 32 + 16, LDS);
#pragma unroll
            for (int i = 0; i < 2; ++i)
#pragma unroll
                for (int j = 0; j < 2; ++j)
                    wmma::mma_sync(acc[i][j], af[i], bf[j], acc[i][j]);
        }
        __syncthreads();
    }

#pragma unroll
    for (int i = 0; i < 2; ++i)
#pragma unroll
        for (int j = 0; j < 2; ++j)
            wmma::store_matrix_sync(Cs + (wy * 32 + i * 16) * LDS + wx * 32 + j * 16,
                                    acc[i][j], LDS, wmma::mem_row_major);
    __syncthreads();

    if (a_ok) {
#pragma unroll
        for (int c = 0; c < 32; c += 4) {
            int col = col0 + lq + c;
            float4 o;
            o.x = Cs[lr * LDS + lq + c + 0];
            o.y = Cs[lr * LDS + lq + c + 1];
            o.z = Cs[lr * LDS + lq + c + 2];
            o.w = Cs[lr * LDS + lq + c + 3];
            *reinterpret_cast<float4*>(g_xacc + (size_t)a_m * DHID + col) = o;
        }
    }
}

// ---------------------------------------------------------------------------
// gemm1_bot (HMMA): xh = fp16( relu( hNh @ W1h[128:256] + g_xacc + b1 ) )
// ---------------------------------------------------------------------------
__global__ __launch_bounds__(128)
void gemm1_bot_kernel(const float* __restrict__ bias) {
    constexpr int LDS = 72;
    __shared__ __align__(16) char sm[64 * LDS * 4];
    __half* As = reinterpret_cast<__half*>(sm);
    __half* Bs = reinterpret_cast<__half*>(sm) + 64 * LDS;
    float*  Cs = reinterpret_cast<float*>(sm);

    int tid  = threadIdx.x;
    int wid  = tid >> 5;
    int row0 = blockIdx.x * 64;
    int col0 = blockIdx.y * 64;
    int wy = wid >> 1, wx = wid & 1;
    int lr = tid >> 1;
    int lq = (tid & 1) * 32;

    wmma::fragment<wmma::accumulator, 16, 16, 16, float> acc[2][2];
#pragma unroll
    for (int i = 0; i < 2; ++i)
#pragma unroll
        for (int j = 0; j < 2; ++j)
            wmma::fill_fragment(acc[i][j], 0.0f);

    int  a_m  = row0 + lr;
    bool a_ok = (a_m < NNODES);

    for (int kb = 0; kb < 128; kb += 64) {
        const __half* abase = g_hNh + (size_t)a_m * DIN + kb;
        uint4 av[4] = {};
        if (a_ok) {
#pragma unroll
            for (int q = 0; q < 4; ++q)
                av[q] = reinterpret_cast<const uint4*>(abase + lq)[q];
        }
#pragma unroll
        for (int q = 0; q < 4; ++q)
            reinterpret_cast<uint4*>(As + lr * LDS + lq)[q] = av[q];

        const __half* wb = g_W1h + (size_t)(128 + kb + lr) * DHID + col0 + lq;
#pragma unroll
        for (int q = 0; q < 4; ++q)
            reinterpret_cast<uint4*>(Bs + lr * LDS + lq)[q] =
                reinterpret_cast<const uint4*>(wb)[q];

        __syncthreads();

#pragma unroll
        for (int ks = 0; ks < 4; ++ks) {
            wmma::fragment<wmma::matrix_a, 16, 16, 16, __half, wmma::row_major> af[2];
            wmma::fragment<wmma::matrix_b, 16, 16, 16, __half, wmma::row_major> bf[2];
            wmma::load_matrix_sync(af[0], As + (wy * 32 +  0) * LDS + ks * 16, LDS);
            wmma::load_matrix_sync(af[1], As + (wy * 32 + 16) * LDS + ks * 16, LDS);
            wmma::load_matrix_sync(bf[0], Bs + (ks * 16) * LDS + wx * 32 +  0, LDS);
            wmma::load_matrix_sync(bf[1], Bs + (ks * 16) * LDS + wx * 32 + 16, LDS);
#pragma unroll
            for (int i = 0; i < 2; ++i)
#pragma unroll
                for (int j = 0; j < 2; ++j)
                    wmma::mma_sync(acc[i][j], af[i], bf[j], acc[i][j]);
        }
        __syncthreads();
    }

#pragma unroll
    for (int i = 0; i < 2; ++i)
#pragma unroll
        for (int j = 0; j < 2; ++j)
            wmma::store_matrix_sync(Cs + (wy * 32 + i * 16) * LDS + wx * 32 + j * 16,
                                    acc[i][j], LDS, wmma::mem_row_major);
    __syncthreads();

    if (a_ok) {
#pragma unroll
        for (int c = 0; c < 32; c += 4) {
            int col = col0 + lq + c;
            float4 xa = *reinterpret_cast<const float4*>(g_xacc + (size_t)a_m * DHID + col);
            float v0 = fmaxf(Cs[lr * LDS + lq + c + 0] + xa.x + bias[col + 0], 0.f);
            float v1 = fmaxf(Cs[lr * LDS + lq + c + 1] + xa.y + bias[col + 1], 0.f);
            float v2 = fmaxf(Cs[lr * LDS + lq + c + 2] + xa.z + bias[col + 2], 0.f);
            float v3 = fmaxf(Cs[lr * LDS + lq + c + 3] + xa.w + bias[col + 3], 0.f);
            __half2 q0 = __floats2half2_rn(v0, v1);
            __half2 q1 = __floats2half2_rn(v2, v3);
            uint2 pk;
            pk.x = *reinterpret_cast<unsigned*>(&q0);
            pk.y = *reinterpret_cast<unsigned*>(&q1);
            *reinterpret_cast<uint2*>(g_xh + (size_t)a_m * DHID + col) = pk;
        }
    }
}

// ---------------------------------------------------------------------------
// gemm2 (HMMA): blockIdx.y==0: out = xh @ W2h[0:256] + b2  (fp32 -> d_out)
//               blockIdx.y==1: yh  = xh @ W2h[256:512]     (fp16 -> g_yh)
// ---------------------------------------------------------------------------
__global__ __launch_bounds__(128)
void gemm2_f16_kernel(const float* __restrict__ bias, float* __restrict__ out) {
    constexpr int LDS = 72;
    __shared__ __align__(16) char sm[64 * LDS * 4];
    __half* As = reinterpret_cast<__half*>(sm);
    __half* Bs = reinterpret_cast<__half*>(sm) + 64 * LDS;
    float*  Cs = reinterpret_cast<float*>(sm);

    int tid  = threadIdx.x;
    int wid  = tid >> 5;
    int row0 = blockIdx.x * 64;
    bool top = (blockIdx.y == 0);
    const __half* W = g_W2h + (top ? 0 : (size_t)DHID * DOUT);

    int wy = wid >> 1, wx = wid & 1;
    int lr = tid >> 1;
    int lq = (tid & 1) * 32;

    wmma::fragment<wmma::accumulator, 16, 16, 16, float> acc[2][2];
#pragma unroll
    for (int i = 0; i < 2; ++i)
#pragma unroll
        for (int j = 0; j < 2; ++j)
            wmma::fill_fragment(acc[i][j], 0.0f);

    int  a_m  = row0 + lr;
    bool a_ok = (a_m < NNODES);

    for (int kb = 0; kb < 256; kb += 64) {
        const __half* abase = g_xh + (size_t)a_m * DHID + kb;
        uint4 av[4] = {};
        if (a_ok) {
#pragma unroll
            for (int q = 0; q < 4; ++q)
                av[q] = reinterpret_cast<const uint4*>(abase + lq)[q];
        }
#pragma unroll
        for (int q = 0; q < 4; ++q)
            reinterpret_cast<uint4*>(As + lr * LDS + lq)[q] = av[q];

        const __half* wb = W + (size_t)(kb + lr) * DOUT + lq;
#pragma unroll
        for (int q = 0; q < 4; ++q)
            reinterpret_cast<uint4*>(Bs + lr * LDS + lq)[q] =
                reinterpret_cast<const uint4*>(wb)[q];

        __syncthreads();

#pragma unroll
        for (int ks = 0; ks < 4; ++ks) {
            wmma::fragment<wmma::matrix_a, 16, 16, 16, __half, wmma::row_major> af[2];
            wmma::fragment<wmma::matrix_b, 16, 16, 16, __half, wmma::row_major> bf[2];
            wmma::load_matrix_sync(af[0], As + (wy * 32 +  0) * LDS + ks * 16, LDS);
            wmma::load_matrix_sync(af[1], As + (wy * 32 + 16) * LDS + ks * 16, LDS);
            wmma::load_matrix_sync(bf[0], Bs + (ks * 16) * LDS + wx * 32 +  0, LDS);
            wmma::load_matrix_sync(bf[1], Bs + (ks * 16) * LDS + wx * 32 + 16, LDS);
#pragma unroll
            for (int i = 0; i < 2; ++i)
#pragma unroll
                for (int j = 0; j < 2; ++j)
                    wmma::mma_sync(acc[i][j], af[i], bf[j], acc[i][j]);
        }
        __syncthreads();
    }

#pragma unroll
    for (int i = 0; i < 2; ++i)
#pragma unroll
        for (int j = 0; j < 2; ++j)
            wmma::store_matrix_sync(Cs + (wy * 32 + i * 16) * LDS + wx * 32 + j * 16,
                                    acc[i][j], LDS, wmma::mem_row_major);
    __syncthreads();

    if (a_ok) {
        if (top) {
#pragma unroll
            for (int c = 0; c < 32; c += 4) {
                int col = lq + c;
                float4 o;
                o.x = Cs[lr * LDS + col + 0] + bias[col + 0];
                o.y = Cs[lr * LDS + col + 1] + bias[col + 1];
                o.z = Cs[lr * LDS + col + 2] + bias[col + 2];
                o.w = Cs[lr * LDS + col + 3] + bias[col + 3];
                *reinterpret_cast<float4*>(out + (size_t)a_m * DOUT + col) = o;
            }
        } else {
#pragma unroll
            for (int c = 0; c < 32; c += 2) {
                int col = lq + c;
                __half2 p = __floats2half2_rn(Cs[lr * LDS + col], Cs[lr * LDS + col + 1]);
                *reinterpret_cast<__half2*>(g_yh + (size_t)a_m * DOUT + col) = p;
            }
        }
    }
}

// ---------------------------------------------------------------------------
extern "C" void kernel_launch(void* const* d_in, const int* in_sizes, int n_in,
                              void* d_out, int out_size) {
    const float* h   = (const float*)d_in[0];
    const float* w   = (const float*)d_in[1];
    const int*   src = (const int*)  d_in[2];
    const int*   dst = (const int*)  d_in[3];
    const float* W1  = (const float*)d_in[4];
    const float* b1  = (const float*)d_in[5];
    const float* W2  = (const float*)d_in[6];
    const float* b2  = (const float*)d_in[7];
    float* out = (float*)d_out;

    static cudaStream_t s2 = nullptr;
    static cudaEvent_t  evFork = nullptr, evCvt = nullptr, evTop = nullptr;
    static bool tried = false;
    if (!tried) {
        tried = true;
        if (cudaStreamCreateWithFlags(&s2, cudaStreamNonBlocking) != cudaSuccess) s2 = nullptr;
        if (s2) {
            if (cudaEventCreateWithFlags(&evFork, cudaEventDisableTiming) != cudaSuccess ||
                cudaEventCreateWithFlags(&evCvt,  cudaEventDisableTiming) != cudaSuccess ||
                cudaEventCreateWithFlags(&evTop,  cudaEventDisableTiming) != cudaSuccess) {
                s2 = nullptr;
            }
        }
    }

    int cvt_total = H_HALF2 + W1_HALF2 + W2_HALF2;
    dim3 g1t((NNODES + 63) / 64, DHID / 64);
    dim3 g2d((NNODES + 63) / 64, 2);

    if (s2) {
        // fork: S2 does cvt -> gemm1_top; S1 (stream 0) builds buckets
        cudaEventRecord(evFork, 0);
        cudaStreamWaitEvent(s2, evFork, 0);

        cvt_kernel<<<(cvt_total + 255) / 256, 256, 0, s2>>>(h, W1, W2);
        cudaEventRecord(evCvt, s2);
        gemm1_top_kernel<<<g1t, 128, 0, s2>>>();
        cudaEventRecord(evTop, s2);

        build_kernel<<<(NE + 255) / 256, 256>>>(src, dst, w);

        cudaStreamWaitEvent(0, evCvt, 0);           // gather1 needs g_hh
        gather1_kernel<<<(NNODES + 3) / 4, 256>>>();

        cudaStreamWaitEvent(0, evTop, 0);           // gemm1_bot needs g_xacc
        gemm1_bot_kernel<<<g1t, 128>>>(b1);
    } else {
        cvt_kernel<<<(cvt_total + 255) / 256, 256>>>(h, W1, W2);
        build_kernel<<<(NE + 255) / 256, 256>>>(src, dst, w);
        gemm1_top_kernel<<<g1t, 128>>>();
        gather1_kernel<<<(NNODES + 3) / 4, 256>>>();
        gemm1_bot_kernel<<<g1t, 128>>>(b1);
    }

    // layer 2 via linearity: out = xh@W2_top + b2 ; yh = xh@W2_bot ; out += agg(yh)
    gemm2_f16_kernel<<<g2d, 128>>>(b2, out);
    gather2_kernel<<<(NNODES * 32 + 255) / 256, 256>>>(out);
}

// round 16
// speedup vs baseline: 1.1447x; 1.1447x over previous
#include <cuda_runtime.h>
#include <cuda_fp16.h>
#include <mma.h>
using namespace nvcuda;

static constexpr int NNODES = 10000;
static constexpr int NE     = 640000;
static constexpr int DIN    = 128;
static constexpr int DHID   = 256;
static constexpr int DOUT   = 64;
static constexpr int CAP    = 160;     // per-node bucket capacity (mean deg 64, sigma 8)

static constexpr int H_HALF2  = NNODES * DIN / 2;        // 640000
static constexpr int W1_HALF2 = 2 * DIN * DHID / 2;      // 32768
static constexpr int W2_HALF2 = 2 * DHID * DOUT / 2;     // 16384

// ---- scratch (__device__ globals: allocation-free rule) ----
__device__ int    g_cnt[NNODES];           // zero-init; invariant restored by gather2
__device__ int2   g_edges[NNODES * CAP];   // (src, w bits) bucketed by dst
__device__ __half g_hh [NNODES * DIN];     // h in fp16
__device__ __half g_hNh[NNODES * DIN];     // layer-1 mean aggregate, fp16
__device__ float  g_xacc[NNODES * DHID];   // h @ W1_top (fp32 partial)
__device__ __half g_xh [NNODES * DHID];    // layer-1 output (post relu), fp16
__device__ __half g_yh [NNODES * DOUT];    // x @ W2_bot, fp16
__device__ __half g_W1h[2 * DIN * DHID];   // W1 fp16 [256 x 256]
__device__ __half g_W2h[2 * DHID * DOUT];  // W2 fp16 [512 x 64]

// ---------------------------------------------------------------------------
// build: one pass, no scan.  pos = dst*CAP + rank
// ---------------------------------------------------------------------------
__global__ void build_kernel(const int* __restrict__ src, const int* __restrict__ dst,
                             const float* __restrict__ w) {
    int e = blockIdx.x * blockDim.x + threadIdx.x;
    if (e < NE) {
        int d = dst[e];
        int r = atomicAdd(&g_cnt[d], 1);
        g_edges[d * CAP + r] = make_int2(src[e], __float_as_int(w[e]));
    }
}

// ---------------------------------------------------------------------------
// cvt: h, W1, W2 -> fp16 (one launch)
// ---------------------------------------------------------------------------
__global__ void cvt_kernel(const float* __restrict__ h,
                           const float* __restrict__ W1,
                           const float* __restrict__ W2) {
    int i = blockIdx.x * blockDim.x + threadIdx.x;
    if (i < H_HALF2) {
        float2 v = reinterpret_cast<const float2*>(h)[i];
        reinterpret_cast<__half2*>(g_hh)[i] = __floats2half2_rn(v.x, v.y);
    } else if (i < H_HALF2 + W1_HALF2) {
        int k = i - H_HALF2;
        float2 v = reinterpret_cast<const float2*>(W1)[k];
        reinterpret_cast<__half2*>(g_W1h)[k] = __floats2half2_rn(v.x, v.y);
    } else if (i < H_HALF2 + W1_HALF2 + W2_HALF2) {
        int k = i - H_HALF2 - W1_HALF2;
        float2 v = reinterpret_cast<const float2*>(W2)[k];
        reinterpret_cast<__half2*>(g_W2h)[k] = __floats2half2_rn(v.x, v.y);
    }
}

// ---------------------------------------------------------------------------
// gather helpers
// ---------------------------------------------------------------------------
__device__ __forceinline__ void acc_uint4_f16(float* acc, uint4 r, float w) {
    float2 p0 = __half22float2(*reinterpret_cast<__half2*>(&r.x));
    float2 p1 = __half22float2(*reinterpret_cast<__half2*>(&r.y));
    float2 p2 = __half22float2(*reinterpret_cast<__half2*>(&r.z));
    float2 p3 = __half22float2(*reinterpret_cast<__half2*>(&r.w));
    acc[0] = fmaf(p0.x, w, acc[0]); acc[1] = fmaf(p0.y, w, acc[1]);
    acc[2] = fmaf(p1.x, w, acc[2]); acc[3] = fmaf(p1.y, w, acc[3]);
    acc[4] = fmaf(p2.x, w, acc[4]); acc[5] = fmaf(p2.y, w, acc[5]);
    acc[6] = fmaf(p3.x, w, acc[6]); acc[7] = fmaf(p3.y, w, acc[7]);
}

// ---------------------------------------------------------------------------
// gather1: hNh[n] = fp16( (1/deg) * sum h[src]*w )   (D=128)
// one warp per node; 2 lane-groups of 16, each lane loads uint4 (8 halves)
// ---------------------------------------------------------------------------
__global__ __launch_bounds__(256)
void gather1_kernel() {
    int gw = (blockIdx.x * blockDim.x + threadIdx.x) >> 5;
    if (gw >= NNODES) return;
    int lane = threadIdx.x & 31;
    int grp  = lane >> 4;
    int sub  = lane & 15;
    int deg = g_cnt[gw];
    int s = gw * CAP, e = s + deg;
    float acc[8] = {};

    int j = s;
    for (; j + 3 < e; j += 4) {
        int2 ea = g_edges[j + grp];
        int2 eb = g_edges[j + 2 + grp];
        uint4 ra = *reinterpret_cast<const uint4*>(g_hh + (size_t)ea.x * DIN + sub * 8);
        uint4 rb = *reinterpret_cast<const uint4*>(g_hh + (size_t)eb.x * DIN + sub * 8);
        acc_uint4_f16(acc, ra, __int_as_float(ea.y));
        acc_uint4_f16(acc, rb, __int_as_float(eb.y));
    }
    for (; j < e; j += 2) {
        if (j + grp < e) {
            int2 ea = g_edges[j + grp];
            uint4 ra = *reinterpret_cast<const uint4*>(g_hh + (size_t)ea.x * DIN + sub * 8);
            acc_uint4_f16(acc, ra, __int_as_float(ea.y));
        }
    }

#pragma unroll
    for (int k = 0; k < 8; ++k)
        acc[k] += __shfl_down_sync(0xffffffffu, acc[k], 16);

    if (lane < 16) {
        float inv = (deg > 0) ? 1.0f / (float)deg : 0.0f;
        __half2 q0 = __floats2half2_rn(acc[0] * inv, acc[1] * inv);
        __half2 q1 = __floats2half2_rn(acc[2] * inv, acc[3] * inv);
        __half2 q2 = __floats2half2_rn(acc[4] * inv, acc[5] * inv);
        __half2 q3 = __floats2half2_rn(acc[6] * inv, acc[7] * inv);
        uint4 pk;
        pk.x = *reinterpret_cast<unsigned*>(&q0);
        pk.y = *reinterpret_cast<unsigned*>(&q1);
        pk.z = *reinterpret_cast<unsigned*>(&q2);
        pk.w = *reinterpret_cast<unsigned*>(&q3);
        *reinterpret_cast<uint4*>(g_hNh + (size_t)gw * DIN + sub * 8) = pk;
    }
}

// ---------------------------------------------------------------------------
// gather2: out[n] += (1/deg) * sum y[src]*w     (D=64);  resets g_cnt
// ---------------------------------------------------------------------------
__global__ __launch_bounds__(256)
void gather2_kernel(float* __restrict__ out) {
    int gw = (blockIdx.x * blockDim.x + threadIdx.x) >> 5;
    if (gw >= NNODES) return;
    int lane = threadIdx.x & 31;
    int grp  = lane >> 3;
    int sub  = lane & 7;
    int deg = g_cnt[gw];
    int s = gw * CAP, e = s + deg;
    float acc[8] = {};

    int j = s;
    for (; j + 7 < e; j += 8) {
        int2 ea = g_edges[j + grp];
        int2 eb = g_edges[j + 4 + grp];
        uint4 ra = *reinterpret_cast<const uint4*>(g_yh + (size_t)ea.x * DOUT + sub * 8);
        uint4 rb = *reinterpret_cast<const uint4*>(g_yh + (size_t)eb.x * DOUT + sub * 8);
        acc_uint4_f16(acc, ra, __int_as_float(ea.y));
        acc_uint4_f16(acc, rb, __int_as_float(eb.y));
    }
    for (; j < e; j += 4) {
        if (j + grp < e) {
            int2 ea = g_edges[j + grp];
            uint4 ra = *reinterpret_cast<const uint4*>(g_yh + (size_t)ea.x * DOUT + sub * 8);
            acc_uint4_f16(acc, ra, __int_as_float(ea.y));
        }
    }

#pragma unroll
    for (int k = 0; k < 8; ++k) {
        acc[k] += __shfl_down_sync(0xffffffffu, acc[k], 16);
        acc[k] += __shfl_down_sync(0xffffffffu, acc[k], 8);
    }

    if (lane == 0) g_cnt[gw] = 0;   // restore zero-invariant for next invocation

    if (lane < 8) {
        float inv = (deg > 0) ? 1.0f / (float)deg : 0.0f;
        float* op = out + (size_t)gw * DOUT + sub * 8;
        float4 c0 = *reinterpret_cast<float4*>(op);
        float4 c1 = *reinterpret_cast<float4*>(op + 4);
        c0.x = fmaf(acc[0], inv, c0.x); c0.y = fmaf(acc[1], inv, c0.y);
        c0.z = fmaf(acc[2], inv, c0.z); c0.w = fmaf(acc[3], inv, c0.w);
        c1.x = fmaf(acc[4], inv, c1.x); c1.y = fmaf(acc[5], inv, c1.y);
        c1.z = fmaf(acc[6], inv, c1.z); c1.w = fmaf(acc[7], inv, c1.w);
        *reinterpret_cast<float4*>(op)     = c0;
        *reinterpret_cast<float4*>(op + 4) = c1;
    }
}

// ---------------------------------------------------------------------------
// gemm1_top (HMMA): g_xacc = hh @ W1h[0:128]   (fp32, no bias)
// ---------------------------------------------------------------------------
__global__ __launch_bounds__(128)
void gemm1_top_kernel() {
    constexpr int LDS = 72;
    __shared__ __align__(16) char sm[64 * LDS * 4];
    __half* As = reinterpret_cast<__half*>(sm);
    __half* Bs = reinterpret_cast<__half*>(sm) + 64 * LDS;
    float*  Cs = reinterpret_cast<float*>(sm);

    int tid  = threadIdx.x;
    int wid  = tid >> 5;
    int row0 = blockIdx.x * 64;
    int col0 = blockIdx.y * 64;
    int wy = wid >> 1, wx = wid & 1;
    int lr = tid >> 1;
    int lq = (tid & 1) * 32;

    wmma::fragment<wmma::accumulator, 16, 16, 16, float> acc[2][2];
#pragma unroll
    for (int i = 0; i < 2; ++i)
#pragma unroll
        for (int j = 0; j < 2; ++j)
            wmma::fill_fragment(acc[i][j], 0.0f);

    int  a_m  = row0 + lr;
    bool a_ok = (a_m < NNODES);

    for (int kb = 0; kb < 128; kb += 64) {
        const __half* abase = g_hh + (size_t)a_m * DIN + kb;
        uint4 av[4] = {};
        if (a_ok) {
#pragma unroll
            for (int q = 0; q < 4; ++q)
                av[q] = reinterpret_cast<const uint4*>(abase + lq)[q];
        }
#pragma unroll
        for (int q = 0; q < 4; ++q)
            reinterpret_cast<uint4*>(As + lr * LDS + lq)[q] = av[q];

        const __half* wb = g_W1h + (size_t)(kb + lr) * DHID + col0 + lq;
#pragma unroll
        for (int q = 0; q < 4; ++q)
            reinterpret_cast<uint4*>(Bs + lr * LDS + lq)[q] =
                reinterpret_cast<const uint4*>(wb)[q];

        __syncthreads();

#pragma unroll
        for (int ks = 0; ks < 4; ++ks) {
            wmma::fragment<wmma::matrix_a, 16, 16, 16, __half, wmma::row_major> af[2];
            wmma::fragment<wmma::matrix_b, 16, 16, 16, __half, wmma::row_major> bf[2];
            wmma::load_matrix_sync(af[0], As + (wy * 32 +  0) * LDS + ks * 16, LDS);
            wmma::load_matrix_sync(af[1], As + (wy * 32 + 16) * LDS + ks * 16, LDS);
            wmma::load_matrix_sync(bf[0], Bs + (ks * 16) * LDS + wx * 32 +  0, LDS);
            wmma::load_matrix_sync(bf[1], Bs + (ks * 16) * LDS + wx * 32 + 16, LDS);
#pragma unroll
            for (int i = 0; i < 2; ++i)
#pragma unroll
                for (int j = 0; j < 2; ++j)
                    wmma::mma_sync(acc[i][j], af[i], bf[j], acc[i][j]);
        }
        __syncthreads();
    }

#pragma unroll
    for (int i = 0; i < 2; ++i)
#pragma unroll
        for (int j = 0; j < 2; ++j)
            wmma::store_matrix_sync(Cs + (wy * 32 + i * 16) * LDS + wx * 32 + j * 16,
                                    acc[i][j], LDS, wmma::mem_row_major);
    __syncthreads();

    if (a_ok) {
#pragma unroll
        for (int c = 0; c < 32; c += 4) {
            int col = col0 + lq + c;
            float4 o;
            o.x = Cs[lr * LDS + lq + c + 0];
            o.y = Cs[lr * LDS + lq + c + 1];
            o.z = Cs[lr * LDS + lq + c + 2];
            o.w = Cs[lr * LDS + lq + c + 3];
            *reinterpret_cast<float4*>(g_xacc + (size_t)a_m * DHID + col) = o;
        }
    }
}

// ---------------------------------------------------------------------------
// gemm1_bot (HMMA): xh = fp16( relu( hNh @ W1h[128:256] + g_xacc + b1 ) )
// ---------------------------------------------------------------------------
__global__ __launch_bounds__(128)
void gemm1_bot_kernel(const float* __restrict__ bias) {
    constexpr int LDS = 72;
    __shared__ __align__(16) char sm[64 * LDS * 4];
    __half* As = reinterpret_cast<__half*>(sm);
    __half* Bs = reinterpret_cast<__half*>(sm) + 64 * LDS;
    float*  Cs = reinterpret_cast<float*>(sm);

    int tid  = threadIdx.x;
    int wid  = tid >> 5;
    int row0 = blockIdx.x * 64;
    int col0 = blockIdx.y * 64;
    int wy = wid >> 1, wx = wid & 1;
    int lr = tid >> 1;
    int lq = (tid & 1) * 32;

    wmma::fragment<wmma::accumulator, 16, 16, 16, float> acc[2][2];
#pragma unroll
    for (int i = 0; i < 2; ++i)
#pragma unroll
        for (int j = 0; j < 2; ++j)
            wmma::fill_fragment(acc[i][j], 0.0f);

    int  a_m  = row0 + lr;
    bool a_ok = (a_m < NNODES);

    for (int kb = 0; kb < 128; kb += 64) {
        const __half* abase = g_hNh + (size_t)a_m * DIN + kb;
        uint4 av[4] = {};
        if (a_ok) {
#pragma unroll
            for (int q = 0; q < 4; ++q)
                av[q] = reinterpret_cast<const uint4*>(abase + lq)[q];
        }
#pragma unroll
        for (int q = 0; q < 4; ++q)
            reinterpret_cast<uint4*>(As + lr * LDS + lq)[q] = av[q];

        const __half* wb = g_W1h + (size_t)(128 + kb + lr) * DHID + col0 + lq;
#pragma unroll
        for (int q = 0; q < 4; ++q)
            reinterpret_cast<uint4*>(Bs + lr * LDS + lq)[q] =
                reinterpret_cast<const uint4*>(wb)[q];

        __syncthreads();

#pragma unroll
        for (int ks = 0; ks < 4; ++ks) {
            wmma::fragment<wmma::matrix_a, 16, 16, 16, __half, wmma::row_major> af[2];
            wmma::fragment<wmma::matrix_b, 16, 16, 16, __half, wmma::row_major> bf[2];
            wmma::load_matrix_sync(af[0], As + (wy * 32 +  0) * LDS + ks * 16, LDS);
            wmma::load_matrix_sync(af[1], As + (wy * 32 + 16) * LDS + ks * 16, LDS);
            wmma::load_matrix_sync(bf[0], Bs + (ks * 16) * LDS + wx * 32 +  0, LDS);
            wmma::load_matrix_sync(bf[1], Bs + (ks * 16) * LDS + wx * 32 + 16, LDS);
#pragma unroll
            for (int i = 0; i < 2; ++i)
#pragma unroll
                for (int j = 0; j < 2; ++j)
                    wmma::mma_sync(acc[i][j], af[i], bf[j], acc[i][j]);
        }
        __syncthreads();
    }

#pragma unroll
    for (int i = 0; i < 2; ++i)
#pragma unroll
        for (int j = 0; j < 2; ++j)
            wmma::store_matrix_sync(Cs + (wy * 32 + i * 16) * LDS + wx * 32 + j * 16,
                                    acc[i][j], LDS, wmma::mem_row_major);
    __syncthreads();

    if (a_ok) {
#pragma unroll
        for (int c = 0; c < 32; c += 4) {
            int col = col0 + lq + c;
            float4 xa = *reinterpret_cast<const float4*>(g_xacc + (size_t)a_m * DHID + col);
            float v0 = fmaxf(Cs[lr * LDS + lq + c + 0] + xa.x + bias[col + 0], 0.f);
            float v1 = fmaxf(Cs[lr * LDS + lq + c + 1] + xa.y + bias[col + 1], 0.f);
            float v2 = fmaxf(Cs[lr * LDS + lq + c + 2] + xa.z + bias[col + 2], 0.f);
            float v3 = fmaxf(Cs[lr * LDS + lq + c + 3] + xa.w + bias[col + 3], 0.f);
            __half2 q0 = __floats2half2_rn(v0, v1);
            __half2 q1 = __floats2half2_rn(v2, v3);
            uint2 pk;
            pk.x = *reinterpret_cast<unsigned*>(&q0);
            pk.y = *reinterpret_cast<unsigned*>(&q1);
            *reinterpret_cast<uint2*>(g_xh + (size_t)a_m * DHID + col) = pk;
        }
    }
}

// ---------------------------------------------------------------------------
// gemm2 (HMMA): blockIdx.y==0: out = xh @ W2h[0:256] + b2  (fp32 -> d_out)
//               blockIdx.y==1: yh  = xh @ W2h[256:512]     (fp16 -> g_yh)
// ---------------------------------------------------------------------------
__global__ __launch_bounds__(128)
void gemm2_f16_kernel(const float* __restrict__ bias, float* __restrict__ out) {
    constexpr int LDS = 72;
    __shared__ __align__(16) char sm[64 * LDS * 4];
    __half* As = reinterpret_cast<__half*>(sm);
    __half* Bs = reinterpret_cast<__half*>(sm) + 64 * LDS;
    float*  Cs = reinterpret_cast<float*>(sm);

    int tid  = threadIdx.x;
    int wid  = tid >> 5;
    int row0 = blockIdx.x * 64;
    bool top = (blockIdx.y == 0);
    const __half* W = g_W2h + (top ? 0 : (size_t)DHID * DOUT);

    int wy = wid >> 1, wx = wid & 1;
    int lr = tid >> 1;
    int lq = (tid & 1) * 32;

    wmma::fragment<wmma::accumulator, 16, 16, 16, float> acc[2][2];
#pragma unroll
    for (int i = 0; i < 2; ++i)
#pragma unroll
        for (int j = 0; j < 2; ++j)
            wmma::fill_fragment(acc[i][j], 0.0f);

    int  a_m  = row0 + lr;
    bool a_ok = (a_m < NNODES);

    for (int kb = 0; kb < 256; kb += 64) {
        const __half* abase = g_xh + (size_t)a_m * DHID + kb;
        uint4 av[4] = {};
        if (a_ok) {
#pragma unroll
            for (int q = 0; q < 4; ++q)
                av[q] = reinterpret_cast<const uint4*>(abase + lq)[q];
        }
#pragma unroll
        for (int q = 0; q < 4; ++q)
            reinterpret_cast<uint4*>(As + lr * LDS + lq)[q] = av[q];

        const __half* wb = W + (size_t)(kb + lr) * DOUT + lq;
#pragma unroll
        for (int q = 0; q < 4; ++q)
            reinterpret_cast<uint4*>(Bs + lr * LDS + lq)[q] =
                reinterpret_cast<const uint4*>(wb)[q];

        __syncthreads();

#pragma unroll
        for (int ks = 0; ks < 4; ++ks) {
            wmma::fragment<wmma::matrix_a, 16, 16, 16, __half, wmma::row_major> af[2];
            wmma::fragment<wmma::matrix_b, 16, 16, 16, __half, wmma::row_major> bf[2];
            wmma::load_matrix_sync(af[0], As + (wy * 32 +  0) * LDS + ks * 16, LDS);
            wmma::load_matrix_sync(af[1], As + (wy * 32 + 16) * LDS + ks * 16, LDS);
            wmma::load_matrix_sync(bf[0], Bs + (ks * 16) * LDS + wx * 32 +  0, LDS);
            wmma::load_matrix_sync(bf[1], Bs + (ks * 16) * LDS + wx * 32 + 16, LDS);
#pragma unroll
            for (int i = 0; i < 2; ++i)
#pragma unroll
                for (int j = 0; j < 2; ++j)
                    wmma::mma_sync(acc[i][j], af[i], bf[j], acc[i][j]);
        }
        __syncthreads();
    }

#pragma unroll
    for (int i = 0; i < 2; ++i)
#pragma unroll
        for (int j = 0; j < 2; ++j)
            wmma::store_matrix_sync(Cs + (wy * 32 + i * 16) * LDS + wx * 32 + j * 16,
                                    acc[i][j], LDS, wmma::mem_row_major);
    __syncthreads();

    if (a_ok) {
        if (top) {
#pragma unroll
            for (int c = 0; c < 32; c += 4) {
                int col = lq + c;
                float4 o;
                o.x = Cs[lr * LDS + col + 0] + bias[col + 0];
                o.y = Cs[lr * LDS + col + 1] + bias[col + 1];
                o.z = Cs[lr * LDS + col + 2] + bias[col + 2];
                o.w = Cs[lr * LDS + col + 3] + bias[col + 3];
                *reinterpret_cast<float4*>(out + (size_t)a_m * DOUT + col) = o;
            }
        } else {
#pragma unroll
            for (int c = 0; c < 32; c += 2) {
                int col = lq + c;
                __half2 p = __floats2half2_rn(Cs[lr * LDS + col], Cs[lr * LDS + col + 1]);
                *reinterpret_cast<__half2*>(g_yh + (size_t)a_m * DOUT + col) = p;
            }
        }
    }
}

// ---------------------------------------------------------------------------
extern "C" void kernel_launch(void* const* d_in, const int* in_sizes, int n_in,
                              void* d_out, int out_size) {
    const float* h   = (const float*)d_in[0];
    const float* w   = (const float*)d_in[1];
    const int*   src = (const int*)  d_in[2];
    const int*   dst = (const int*)  d_in[3];
    const float* W1  = (const float*)d_in[4];
    const float* b1  = (const float*)d_in[5];
    const float* W2  = (const float*)d_in[6];
    const float* b2  = (const float*)d_in[7];
    float* out = (float*)d_out;

    static cudaStream_t s2 = nullptr;
    static cudaEvent_t  evFork = nullptr, evCvt = nullptr, evTop = nullptr;
    static bool tried = false;
    if (!tried) {
        tried = true;
        if (cudaStreamCreateWithFlags(&s2, cudaStreamNonBlocking) != cudaSuccess) s2 = nullptr;
        if (s2) {
            if (cudaEventCreateWithFlags(&evFork, cudaEventDisableTiming) != cudaSuccess ||
                cudaEventCreateWithFlags(&evCvt,  cudaEventDisableTiming) != cudaSuccess ||
                cudaEventCreateWithFlags(&evTop,  cudaEventDisableTiming) != cudaSuccess) {
                s2 = nullptr;
            }
        }
    }

    int cvt_total = H_HALF2 + W1_HALF2 + W2_HALF2;
    dim3 g1t((NNODES + 63) / 64, DHID / 64);
    dim3 g2d((NNODES + 63) / 64, 2);

    if (s2) {
        // fork: S2 does cvt -> gemm1_top; S1 (stream 0) builds buckets
        cudaEventRecord(evFork, 0);
        cudaStreamWaitEvent(s2, evFork, 0);

        cvt_kernel<<<(cvt_total + 255) / 256, 256, 0, s2>>>(h, W1, W2);
        cudaEventRecord(evCvt, s2);
        gemm1_top_kernel<<<g1t, 128, 0, s2>>>();
        cudaEventRecord(evTop, s2);

        build_kernel<<<(NE + 255) / 256, 256>>>(src, dst, w);

        cudaStreamWaitEvent(0, evCvt, 0);           // gather1 needs g_hh
        gather1_kernel<<<(NNODES * 32 + 255) / 256, 256>>>();

        cudaStreamWaitEvent(0, evTop, 0);           // gemm1_bot needs g_xacc
        gemm1_bot_kernel<<<g1t, 128>>>(b1);
    } else {
        cvt_kernel<<<(cvt_total + 255) / 256, 256>>>(h, W1, W2);
        build_kernel<<<(NE + 255) / 256, 256>>>(src, dst, w);
        gemm1_top_kernel<<<g1t, 128>>>();
        gather1_kernel<<<(NNODES * 32 + 255) / 256, 256>>>();
        gemm1_bot_kernel<<<g1t, 128>>>(b1);
    }

    // layer 2 via linearity: out = xh@W2_top + b2 ; yh = xh@W2_bot ; out += agg(yh)
    gemm2_f16_kernel<<<g2d, 128>>>(b2, out);
    gather2_kernel<<<(NNODES * 32 + 255) / 256, 256>>>(out);
}

// round 17
// speedup vs baseline: 1.1469x; 1.0019x over previous
#include <cuda_runtime.h>
#include <cuda_fp16.h>
#include <mma.h>
using namespace nvcuda;

static constexpr int NNODES = 10000;
static constexpr int NE     = 640000;
static constexpr int DIN    = 128;
static constexpr int DHID   = 256;
static constexpr int DOUT   = 64;
static constexpr int CAP    = 160;     // per-node bucket capacity (mean deg 64, sigma 8)

static constexpr int H_HALF2  = NNODES * DIN / 2;        // 640000 == NE
static constexpr int W1_HALF2 = 2 * DIN * DHID / 2;      // 32768
static constexpr int W2_HALF2 = 2 * DHID * DOUT / 2;     // 16384

// ---- scratch (__device__ globals: allocation-free rule) ----
__device__ int    g_cnt[NNODES];           // zero-init; invariant restored by gather2
__device__ int2   g_edges[NNODES * CAP];   // (src, w bits) bucketed by dst
__device__ __half g_hh [NNODES * DIN];     // h in fp16
__device__ __half g_hNh[NNODES * DIN];     // layer-1 mean aggregate, fp16
__device__ float  g_xacc[NNODES * DHID];   // h @ W1_top (fp32 partial)
__device__ __half g_xh [NNODES * DHID];    // layer-1 output (post relu), fp16
__device__ __half g_yh [NNODES * DOUT];    // x @ W2_bot, fp16
__device__ __half g_W1h[2 * DIN * DHID];   // W1 fp16 [256 x 256]
__device__ __half g_W2h[2 * DHID * DOUT];  // W2 fp16 [512 x 64]

// ---------------------------------------------------------------------------
// build_cvt: edge bucket insert + ALL fp32->fp16 conversions, one launch.
// threads [0, NE): edge insert AND h convert (H_HALF2 == NE)
// threads [NE, NE+W1_HALF2): W1 convert
// threads [NE+W1_HALF2, ..+W2_HALF2): W2 convert
// (R9-verified: cvt streaming traffic hides under the atomic-latency-bound fill)
// ---------------------------------------------------------------------------
__global__ void build_cvt_kernel(const int* __restrict__ src, const int* __restrict__ dst,
                                 const float* __restrict__ w,
                                 const float* __restrict__ h,
                                 const float* __restrict__ W1,
                                 const float* __restrict__ W2) {
    int e = blockIdx.x * blockDim.x + threadIdx.x;
    if (e < NE) {
        int d = dst[e];
        int r = atomicAdd(&g_cnt[d], 1);
        g_edges[d * CAP + r] = make_int2(src[e], __float_as_int(w[e]));
        float2 v = reinterpret_cast<const float2*>(h)[e];
        reinterpret_cast<__half2*>(g_hh)[e] = __floats2half2_rn(v.x, v.y);
    } else {
        int i = e - NE;
        if (i < W1_HALF2) {
            float2 v = reinterpret_cast<const float2*>(W1)[i];
            reinterpret_cast<__half2*>(g_W1h)[i] = __floats2half2_rn(v.x, v.y);
        } else if (i < W1_HALF2 + W2_HALF2) {
            int k = i - W1_HALF2;
            float2 v = reinterpret_cast<const float2*>(W2)[k];
            reinterpret_cast<__half2*>(g_W2h)[k] = __floats2half2_rn(v.x, v.y);
        }
    }
}

// ---------------------------------------------------------------------------
// gather helpers
// ---------------------------------------------------------------------------
__device__ __forceinline__ void acc_uint4_f16(float* acc, uint4 r, float w) {
    float2 p0 = __half22float2(*reinterpret_cast<__half2*>(&r.x));
    float2 p1 = __half22float2(*reinterpret_cast<__half2*>(&r.y));
    float2 p2 = __half22float2(*reinterpret_cast<__half2*>(&r.z));
    float2 p3 = __half22float2(*reinterpret_cast<__half2*>(&r.w));
    acc[0] = fmaf(p0.x, w, acc[0]); acc[1] = fmaf(p0.y, w, acc[1]);
    acc[2] = fmaf(p1.x, w, acc[2]); acc[3] = fmaf(p1.y, w, acc[3]);
    acc[4] = fmaf(p2.x, w, acc[4]); acc[5] = fmaf(p2.y, w, acc[5]);
    acc[6] = fmaf(p3.x, w, acc[6]); acc[7] = fmaf(p3.y, w, acc[7]);
}

// ---------------------------------------------------------------------------
// gather1: hNh[n] = fp16( (1/deg) * sum h[src]*w )   (D=128)
// one warp per node; 2 lane-groups of 16, each lane loads uint4 (8 halves)
// ---------------------------------------------------------------------------
__global__ __launch_bounds__(256)
void gather1_kernel() {
    int gw = (blockIdx.x * blockDim.x + threadIdx.x) >> 5;
    if (gw >= NNODES) return;
    int lane = threadIdx.x & 31;
    int grp  = lane >> 4;
    int sub  = lane & 15;
    int deg = g_cnt[gw];
    int s = gw * CAP, e = s + deg;
    float acc[8] = {};

    int j = s;
    for (; j + 3 < e; j += 4) {
        int2 ea = g_edges[j + grp];
        int2 eb = g_edges[j + 2 + grp];
        uint4 ra = *reinterpret_cast<const uint4*>(g_hh + (size_t)ea.x * DIN + sub * 8);
        uint4 rb = *reinterpret_cast<const uint4*>(g_hh + (size_t)eb.x * DIN + sub * 8);
        acc_uint4_f16(acc, ra, __int_as_float(ea.y));
        acc_uint4_f16(acc, rb, __int_as_float(eb.y));
    }
    for (; j < e; j += 2) {
        if (j + grp < e) {
            int2 ea = g_edges[j + grp];
            uint4 ra = *reinterpret_cast<const uint4*>(g_hh + (size_t)ea.x * DIN + sub * 8);
            acc_uint4_f16(acc, ra, __int_as_float(ea.y));
        }
    }

#pragma unroll
    for (int k = 0; k < 8; ++k)
        acc[k] += __shfl_down_sync(0xffffffffu, acc[k], 16);

    if (lane < 16) {
        float inv = (deg > 0) ? 1.0f / (float)deg : 0.0f;
        __half2 q0 = __floats2half2_rn(acc[0] * inv, acc[1] * inv);
        __half2 q1 = __floats2half2_rn(acc[2] * inv, acc[3] * inv);
        __half2 q2 = __floats2half2_rn(acc[4] * inv, acc[5] * inv);
        __half2 q3 = __floats2half2_rn(acc[6] * inv, acc[7] * inv);
        uint4 pk;
        pk.x = *reinterpret_cast<unsigned*>(&q0);
        pk.y = *reinterpret_cast<unsigned*>(&q1);
        pk.z = *reinterpret_cast<unsigned*>(&q2);
        pk.w = *reinterpret_cast<unsigned*>(&q3);
        *reinterpret_cast<uint4*>(g_hNh + (size_t)gw * DIN + sub * 8) = pk;
    }
}

// ---------------------------------------------------------------------------
// gather2: out[n] += (1/deg) * sum y[src]*w     (D=64);  resets g_cnt
// ---------------------------------------------------------------------------
__global__ __launch_bounds__(256)
void gather2_kernel(float* __restrict__ out) {
    int gw = (blockIdx.x * blockDim.x + threadIdx.x) >> 5;
    if (gw >= NNODES) return;
    int lane = threadIdx.x & 31;
    int grp  = lane >> 3;
    int sub  = lane & 7;
    int deg = g_cnt[gw];
    int s = gw * CAP, e = s + deg;
    float acc[8] = {};

    int j = s;
    for (; j + 7 < e; j += 8) {
        int2 ea = g_edges[j + grp];
        int2 eb = g_edges[j + 4 + grp];
        uint4 ra = *reinterpret_cast<const uint4*>(g_yh + (size_t)ea.x * DOUT + sub * 8);
        uint4 rb = *reinterpret_cast<const uint4*>(g_yh + (size_t)eb.x * DOUT + sub * 8);
        acc_uint4_f16(acc, ra, __int_as_float(ea.y));
        acc_uint4_f16(acc, rb, __int_as_float(eb.y));
    }
    for (; j < e; j += 4) {
        if (j + grp < e) {
            int2 ea = g_edges[j + grp];
            uint4 ra = *reinterpret_cast<const uint4*>(g_yh + (size_t)ea.x * DOUT + sub * 8);
            acc_uint4_f16(acc, ra, __int_as_float(ea.y));
        }
    }

#pragma unroll
    for (int k = 0; k < 8; ++k) {
        acc[k] += __shfl_down_sync(0xffffffffu, acc[k], 16);
        acc[k] += __shfl_down_sync(0xffffffffu, acc[k], 8);
    }

    if (lane == 0) g_cnt[gw] = 0;   // restore zero-invariant for next invocation

    if (lane < 8) {
        float inv = (deg > 0) ? 1.0f / (float)deg : 0.0f;
        float* op = out + (size_t)gw * DOUT + sub * 8;
        float4 c0 = *reinterpret_cast<float4*>(op);
        float4 c1 = *reinterpret_cast<float4*>(op + 4);
        c0.x = fmaf(acc[0], inv, c0.x); c0.y = fmaf(acc[1], inv, c0.y);
        c0.z = fmaf(acc[2], inv, c0.z); c0.w = fmaf(acc[3], inv, c0.w);
        c1.x = fmaf(acc[4], inv, c1.x); c1.y = fmaf(acc[5], inv, c1.y);
        c1.z = fmaf(acc[6], inv, c1.z); c1.w = fmaf(acc[7], inv, c1.w);
        *reinterpret_cast<float4*>(op)     = c0;
        *reinterpret_cast<float4*>(op + 4) = c1;
    }
}

// ---------------------------------------------------------------------------
// gemm1_top (HMMA): g_xacc = hh @ W1h[0:128]   (fp32, no bias)
// ---------------------------------------------------------------------------
__global__ __launch_bounds__(128)
void gemm1_top_kernel() {
    constexpr int LDS = 72;
    __shared__ __align__(16) char sm[64 * LDS * 4];
    __half* As = reinterpret_cast<__half*>(sm);
    __half* Bs = reinterpret_cast<__half*>(sm) + 64 * LDS;
    float*  Cs = reinterpret_cast<float*>(sm);

    int tid  = threadIdx.x;
    int wid  = tid >> 5;
    int row0 = blockIdx.x * 64;
    int col0 = blockIdx.y * 64;
    int wy = wid >> 1, wx = wid & 1;
    int lr = tid >> 1;
    int lq = (tid & 1) * 32;

    wmma::fragment<wmma::accumulator, 16, 16, 16, float> acc[2][2];
#pragma unroll
    for (int i = 0; i < 2; ++i)
#pragma unroll
        for (int j = 0; j < 2; ++j)
            wmma::fill_fragment(acc[i][j], 0.0f);

    int  a_m  = row0 + lr;
    bool a_ok = (a_m < NNODES);

    for (int kb = 0; kb < 128; kb += 64) {
        const __half* abase = g_hh + (size_t)a_m * DIN + kb;
        uint4 av[4] = {};
        if (a_ok) {
#pragma unroll
            for (int q = 0; q < 4; ++q)
                av[q] = reinterpret_cast<const uint4*>(abase + lq)[q];
        }
#pragma unroll
        for (int q = 0; q < 4; ++q)
            reinterpret_cast<uint4*>(As + lr * LDS + lq)[q] = av[q];

        const __half* wb = g_W1h + (size_t)(kb + lr) * DHID + col0 + lq;
#pragma unroll
        for (int q = 0; q < 4; ++q)
            reinterpret_cast<uint4*>(Bs + lr * LDS + lq)[q] =
                reinterpret_cast<const uint4*>(wb)[q];

        __syncthreads();

#pragma unroll
        for (int ks = 0; ks < 4; ++ks) {
            wmma::fragment<wmma::matrix_a, 16, 16, 16, __half, wmma::row_major> af[2];
            wmma::fragment<wmma::matrix_b, 16, 16, 16, __half, wmma::row_major> bf[2];
            wmma::load_matrix_sync(af[0], As + (wy * 32 +  0) * LDS + ks * 16, LDS);
            wmma::load_matrix_sync(af[1], As + (wy * 32 + 16) * LDS + ks * 16, LDS);
            wmma::load_matrix_sync(bf[0], Bs + (ks * 16) * LDS + wx * 32 +  0, LDS);
            wmma::load_matrix_sync(bf[1], Bs + (ks * 16) * LDS + wx * 32 + 16, LDS);
#pragma unroll
            for (int i = 0; i < 2; ++i)
#pragma unroll
                for (int j = 0; j < 2; ++j)
                    wmma::mma_sync(acc[i][j], af[i], bf[j], acc[i][j]);
        }
        __syncthreads();
    }

#pragma unroll
    for (int i = 0; i < 2; ++i)
#pragma unroll
        for (int j = 0; j < 2; ++j)
            wmma::store_matrix_sync(Cs + (wy * 32 + i * 16) * LDS + wx * 32 + j * 16,
                                    acc[i][j], LDS, wmma::mem_row_major);
    __syncthreads();

    if (a_ok) {
#pragma unroll
        for (int c = 0; c < 32; c += 4) {
            int col = col0 + lq + c;
            float4 o;
            o.x = Cs[lr * LDS + lq + c + 0];
            o.y = Cs[lr * LDS + lq + c + 1];
            o.z = Cs[lr * LDS + lq + c + 2];
            o.w = Cs[lr * LDS + lq + c + 3];
            *reinterpret_cast<float4*>(g_xacc + (size_t)a_m * DHID + col) = o;
        }
    }
}

// ---------------------------------------------------------------------------
// gemm1_bot (HMMA): xh = fp16( relu( hNh @ W1h[128:256] + g_xacc + b1 ) )
// ---------------------------------------------------------------------------
__global__ __launch_bounds__(128)
void gemm1_bot_kernel(const float* __restrict__ bias) {
    constexpr int LDS = 72;
    __shared__ __align__(16) char sm[64 * LDS * 4];
    __half* As = reinterpret_cast<__half*>(sm);
    __half* Bs = reinterpret_cast<__half*>(sm) + 64 * LDS;
    float*  Cs = reinterpret_cast<float*>(sm);

    int tid  = threadIdx.x;
    int wid  = tid >> 5;
    int row0 = blockIdx.x * 64;
    int col0 = blockIdx.y * 64;
    int wy = wid >> 1, wx = wid & 1;
    int lr = tid >> 1;
    int lq = (tid & 1) * 32;

    wmma::fragment<wmma::accumulator, 16, 16, 16, float> acc[2][2];
#pragma unroll
    for (int i = 0; i < 2; ++i)
#pragma unroll
        for (int j = 0; j < 2; ++j)
            wmma::fill_fragment(acc[i][j], 0.0f);

    int  a_m  = row0 + lr;
    bool a_ok = (a_m < NNODES);

    for (int kb = 0; kb < 128; kb += 64) {
        const __half* abase = g_hNh + (size_t)a_m * DIN + kb;
        uint4 av[4] = {};
        if (a_ok) {
#pragma unroll
            for (int q = 0; q < 4; ++q)
                av[q] = reinterpret_cast<const uint4*>(abase + lq)[q];
        }
#pragma unroll
        for (int q = 0; q < 4; ++q)
            reinterpret_cast<uint4*>(As + lr * LDS + lq)[q] = av[q];

        const __half* wb = g_W1h + (size_t)(128 + kb + lr) * DHID + col0 + lq;
#pragma unroll
        for (int q = 0; q < 4; ++q)
            reinterpret_cast<uint4*>(Bs + lr * LDS + lq)[q] =
                reinterpret_cast<const uint4*>(wb)[q];

        __syncthreads();

#pragma unroll
        for (int ks = 0; ks < 4; ++ks) {
            wmma::fragment<wmma::matrix_a, 16, 16, 16, __half, wmma::row_major> af[2];
            wmma::fragment<wmma::matrix_b, 16, 16, 16, __half, wmma::row_major> bf[2];
            wmma::load_matrix_sync(af[0], As + (wy * 32 +  0) * LDS + ks * 16, LDS);
            wmma::load_matrix_sync(af[1], As + (wy * 32 + 16) * LDS + ks * 16, LDS);
            wmma::load_matrix_sync(bf[0], Bs + (ks * 16) * LDS + wx * 32 +  0, LDS);
            wmma::load_matrix_sync(bf[1], Bs + (ks * 16) * LDS + wx * 32 + 16, LDS);
#pragma unroll
            for (int i = 0; i < 2; ++i)
#pragma unroll
                for (int j = 0; j < 2; ++j)
                    wmma::mma_sync(acc[i][j], af[i], bf[j], acc[i][j]);
        }
        __syncthreads();
    }

#pragma unroll
    for (int i = 0; i < 2; ++i)
#pragma unroll
        for (int j = 0; j < 2; ++j)
            wmma::store_matrix_sync(Cs + (wy * 32 + i * 16) * LDS + wx * 32 + j * 16,
                                    acc[i][j], LDS, wmma::mem_row_major);
    __syncthreads();

    if (a_ok) {
#pragma unroll
        for (int c = 0; c < 32; c += 4) {
            int col = col0 + lq + c;
            float4 xa = *reinterpret_cast<const float4*>(g_xacc + (size_t)a_m * DHID + col);
            float v0 = fmaxf(Cs[lr * LDS + lq + c + 0] + xa.x + bias[col + 0], 0.f);
            float v1 = fmaxf(Cs[lr * LDS + lq + c + 1] + xa.y + bias[col + 1], 0.f);
            float v2 = fmaxf(Cs[lr * LDS + lq + c + 2] + xa.z + bias[col + 2], 0.f);
            float v3 = fmaxf(Cs[lr * LDS + lq + c + 3] + xa.w + bias[col + 3], 0.f);
            __half2 q0 = __floats2half2_rn(v0, v1);
            __half2 q1 = __floats2half2_rn(v2, v3);
            uint2 pk;
            pk.x = *reinterpret_cast<unsigned*>(&q0);
            pk.y = *reinterpret_cast<unsigned*>(&q1);
            *reinterpret_cast<uint2*>(g_xh + (size_t)a_m * DHID + col) = pk;
        }
    }
}

// ---------------------------------------------------------------------------
// gemm2 (HMMA): blockIdx.y==0: out = xh @ W2h[0:256] + b2  (fp32 -> d_out)
//               blockIdx.y==1: yh  = xh @ W2h[256:512]     (fp16 -> g_yh)
// ---------------------------------------------------------------------------
__global__ __launch_bounds__(128)
void gemm2_f16_kernel(const float* __restrict__ bias, float* __restrict__ out) {
    constexpr int LDS = 72;
    __shared__ __align__(16) char sm[64 * LDS * 4];
    __half* As = reinterpret_cast<__half*>(sm);
    __half* Bs = reinterpret_cast<__half*>(sm) + 64 * LDS;
    float*  Cs = reinterpret_cast<float*>(sm);

    int tid  = threadIdx.x;
    int wid  = tid >> 5;
    int row0 = blockIdx.x * 64;
    bool top = (blockIdx.y == 0);
    const __half* W = g_W2h + (top ? 0 : (size_t)DHID * DOUT);

    int wy = wid >> 1, wx = wid & 1;
    int lr = tid >> 1;
    int lq = (tid & 1) * 32;

    wmma::fragment<wmma::accumulator, 16, 16, 16, float> acc[2][2];
#pragma unroll
    for (int i = 0; i < 2; ++i)
#pragma unroll
        for (int j = 0; j < 2; ++j)
            wmma::fill_fragment(acc[i][j], 0.0f);

    int  a_m  = row0 + lr;
    bool a_ok = (a_m < NNODES);

    for (int kb = 0; kb < 256; kb += 64) {
        const __half* abase = g_xh + (size_t)a_m * DHID + kb;
        uint4 av[4] = {};
        if (a_ok) {
#pragma unroll
            for (int q = 0; q < 4; ++q)
                av[q] = reinterpret_cast<const uint4*>(abase + lq)[q];
        }
#pragma unroll
        for (int q = 0; q < 4; ++q)
            reinterpret_cast<uint4*>(As + lr * LDS + lq)[q] = av[q];

        const __half* wb = W + (size_t)(kb + lr) * DOUT + lq;
#pragma unroll
        for (int q = 0; q < 4; ++q)
            reinterpret_cast<uint4*>(Bs + lr * LDS + lq)[q] =
                reinterpret_cast<const uint4*>(wb)[q];

        __syncthreads();

#pragma unroll
        for (int ks = 0; ks < 4; ++ks) {
            wmma::fragment<wmma::matrix_a, 16, 16, 16, __half, wmma::row_major> af[2];
            wmma::fragment<wmma::matrix_b, 16, 16, 16, __half, wmma::row_major> bf[2];
            wmma::load_matrix_sync(af[0], As + (wy * 32 +  0) * LDS + ks * 16, LDS);
            wmma::load_matrix_sync(af[1], As + (wy * 32 + 16) * LDS + ks * 16, LDS);
            wmma::load_matrix_sync(bf[0], Bs + (ks * 16) * LDS + wx * 32 +  0, LDS);
            wmma::load_matrix_sync(bf[1], Bs + (ks * 16) * LDS + wx * 32 + 16, LDS);
#pragma unroll
            for (int i = 0; i < 2; ++i)
#pragma unroll
                for (int j = 0; j < 2; ++j)
                    wmma::mma_sync(acc[i][j], af[i], bf[j], acc[i][j]);
        }
        __syncthreads();
    }

#pragma unroll
    for (int i = 0; i < 2; ++i)
#pragma unroll
        for (int j = 0; j < 2; ++j)
            wmma::store_matrix_sync(Cs + (wy * 32 + i * 16) * LDS + wx * 32 + j * 16,
                                    acc[i][j], LDS, wmma::mem_row_major);
    __syncthreads();

    if (a_ok) {
        if (top) {
#pragma unroll
            for (int c = 0; c < 32; c += 4) {
                int col = lq + c;
                float4 o;
                o.x = Cs[lr * LDS + col + 0] + bias[col + 0];
                o.y = Cs[lr * LDS + col + 1] + bias[col + 1];
                o.z = Cs[lr * LDS + col + 2] + bias[col + 2];
                o.w = Cs[lr * LDS + col + 3] + bias[col + 3];
                *reinterpret_cast<float4*>(out + (size_t)a_m * DOUT + col) = o;
            }
        } else {
#pragma unroll
            for (int c = 0; c < 32; c += 2) {
                int col = lq + c;
                __half2 p = __floats2half2_rn(Cs[lr * LDS + col], Cs[lr * LDS + col + 1]);
                *reinterpret_cast<__half2*>(g_yh + (size_t)a_m * DOUT + col) = p;
            }
        }
    }
}

// ---------------------------------------------------------------------------
extern "C" void kernel_launch(void* const* d_in, const int* in_sizes, int n_in,
                              void* d_out, int out_size) {
    const float* h   = (const float*)d_in[0];
    const float* w   = (const float*)d_in[1];
    const int*   src = (const int*)  d_in[2];
    const int*   dst = (const int*)  d_in[3];
    const float* W1  = (const float*)d_in[4];
    const float* b1  = (const float*)d_in[5];
    const float* W2  = (const float*)d_in[6];
    const float* b2  = (const float*)d_in[7];
    float* out = (float*)d_out;

    static cudaStream_t s2 = nullptr;
    static cudaEvent_t  evBuild = nullptr, evTop = nullptr;
    static bool tried = false;
    if (!tried) {
        tried = true;
        if (cudaStreamCreateWithFlags(&s2, cudaStreamNonBlocking) != cudaSuccess) s2 = nullptr;
        if (s2) {
            if (cudaEventCreateWithFlags(&evBuild, cudaEventDisableTiming) != cudaSuccess ||
                cudaEventCreateWithFlags(&evTop,   cudaEventDisableTiming) != cudaSuccess) {
                s2 = nullptr;
            }
        }
    }

    int total = NE + W1_HALF2 + W2_HALF2;
    dim3 g1t((NNODES + 63) / 64, DHID / 64);
    dim3 g2d((NNODES + 63) / 64, 2);

    if (s2) {
        // build+cvt on stream 0, then fork: gemm1_top (s2) overlaps gather1 (s0)
        build_cvt_kernel<<<(total + 255) / 256, 256>>>(src, dst, w, h, W1, W2);
        cudaEventRecord(evBuild, 0);
        cudaStreamWaitEvent(s2, evBuild, 0);

        gemm1_top_kernel<<<g1t, 128, 0, s2>>>();
        cudaEventRecord(evTop, s2);

        gather1_kernel<<<(NNODES * 32 + 255) / 256, 256>>>();

        cudaStreamWaitEvent(0, evTop, 0);           // gemm1_bot needs g_xacc
        gemm1_bot_kernel<<<g1t, 128>>>(b1);
    } else {
        build_cvt_kernel<<<(total + 255) / 256, 256>>>(src, dst, w, h, W1, W2);
        gemm1_top_kernel<<<g1t, 128>>>();
        gather1_kernel<<<(NNODES * 32 + 255) / 256, 256>>>();
        gemm1_bot_kernel<<<g1t, 128>>>(b1);
    }

    // layer 2 via linearity: out = xh@W2_top + b2 ; yh = xh@W2_bot ; out += agg(yh)
    gemm2_f16_kernel<<<g2d, 128>>>(b2, out);
    gather2_kernel<<<(NNODES * 32 + 255) / 256, 256>>>(out);
}